// round 14
// baseline (speedup 1.0000x reference)
#include <cuda_runtime.h>
#include <cuda_fp16.h>
#include <math.h>
#include <stdint.h>

// Shapes (fixed): B=32, T=128, V=32000, E=512, H=1024, 4H=4096
#define BB 32
#define TT 128
#define VV 32000
#define EE 512
#define HH 1024
#define GG 4096
#define MM 4096   // T*B rows

// ------------------------- static device scratch ---------------------------
__device__ float  g_xz[(size_t)MM * GG];        // emb[X]@W + b  (64 MB)
__device__ __half g_hs_h[(size_t)MM * HH];      // hs fp16 archive (8 MB) — also h state
__device__ __half g_h016[BB * HH];              // h0 fp16
__device__ __half g_wdt_h[(size_t)VV * HH];     // Wd^T fp16 [V][K] (64 MB)
__device__ __half g_a16[(size_t)MM * EE];       // gathered emb fp16 (4 MB)
__device__ __half g_wt16[(size_t)GG * EE];      // W^T fp16 [4H][E] (4 MB)
__device__ __half g_ut16[(size_t)GG * HH];      // U^T fp16 [4H][H] (8 MB)
__device__ unsigned g_flags[128];               // distributed step barrier

__device__ __forceinline__ float sigm(float x) { return 1.0f / (1.0f + expf(-x)); }

__device__ __forceinline__ uint32_t smem_u32(const void* p) {
    uint32_t a;
    asm("{ .reg .u64 t; cvta.to.shared.u64 t, %1; cvt.u32.u64 %0, t; }"
        : "=r"(a) : "l"(p));
    return a;
}
__device__ __forceinline__ void cpa16(uint32_t d, const void* s) {
    asm volatile("cp.async.cg.shared.global [%0], [%1], 16;" :: "r"(d), "l"(s));
}
#define SWZ(x) ((x) ^ (((x) >> 3) & 0x70))

// ---------------------------------------------------------------------------
__global__ void init_bar_kernel() {
    if (threadIdx.x < 128) g_flags[threadIdx.x] = 0u;
}

// ---------------------------------------------------------------------------
// Prep A: gather emb rows -> fp16, row r = t*32+b
// ---------------------------------------------------------------------------
__global__ void __launch_bounds__(128) gather_conv_kernel(
    const int* __restrict__ X, const float* __restrict__ emb)
{
    const int r = blockIdx.x;
    const int t = r >> 5, b = r & 31;
    const int e = X[b * TT + t];
    float4 v = ((const float4*)(emb + (size_t)e * EE))[threadIdx.x];
    __half2 h01 = __floats2half2_rn(v.x, v.y);
    __half2 h23 = __floats2half2_rn(v.z, v.w);
    uint2 pk;
    pk.x = *(uint32_t*)&h01;
    pk.y = *(uint32_t*)&h23;
    *(uint2*)(g_a16 + (size_t)r * EE + threadIdx.x * 4) = pk;
}

// ---------------------------------------------------------------------------
// Prep B: W [E=512][4H] -> W^T fp16 [4H][E]
// ---------------------------------------------------------------------------
__global__ void __launch_bounds__(256) wt_conv_kernel(const float* __restrict__ W)
{
    __shared__ float tb[32][33];
    const int n0 = blockIdx.x * 32;
    const int k0 = blockIdx.y * 32;
    const int tx = threadIdx.x & 31;
    const int ty0 = threadIdx.x >> 5;
#pragma unroll
    for (int ty = ty0; ty < 32; ty += 8)
        tb[ty][tx] = W[(size_t)(k0 + ty) * GG + n0 + tx];
    __syncthreads();
#pragma unroll
    for (int ty = ty0; ty < 32; ty += 8)
        g_wt16[(size_t)(n0 + ty) * EE + k0 + tx] = __float2half(tb[tx][ty]);
}

// ---------------------------------------------------------------------------
// Prep B2: U [H=1024][4H] -> U^T fp16 [4H][H]
// ---------------------------------------------------------------------------
__global__ void __launch_bounds__(256) ut_conv_kernel(const float* __restrict__ U)
{
    __shared__ float tb[32][33];
    const int n0 = blockIdx.x * 32;
    const int k0 = blockIdx.y * 32;
    const int tx = threadIdx.x & 31;
    const int ty0 = threadIdx.x >> 5;
#pragma unroll
    for (int ty = ty0; ty < 32; ty += 8)
        tb[ty][tx] = U[(size_t)(k0 + ty) * GG + n0 + tx];
    __syncthreads();
#pragma unroll
    for (int ty = ty0; ty < 32; ty += 8)
        g_ut16[(size_t)(n0 + ty) * HH + k0 + tx] = __float2half(tb[tx][ty]);
}

// ---------------------------------------------------------------------------
// Prep C: Wd [K=1024][V] -> Wd^T fp16 [V][K]
// ---------------------------------------------------------------------------
__global__ void __launch_bounds__(256) wd_split_kernel(const float* __restrict__ Wd)
{
    __shared__ float tb[32][33];
    const int v0 = blockIdx.x * 32;
    const int k0 = blockIdx.y * 32;
    const int tx = threadIdx.x & 31;
    const int ty0 = threadIdx.x >> 5;
#pragma unroll
    for (int ty = ty0; ty < 32; ty += 8)
        tb[ty][tx] = Wd[(size_t)(k0 + ty) * VV + v0 + tx];
    __syncthreads();
#pragma unroll
    for (int ty = ty0; ty < 32; ty += 8)
        g_wdt_h[(size_t)(v0 + ty) * HH + k0 + tx] = __float2half(tb[tx][ty]);
}

// ---------------------------------------------------------------------------
// Prep D: h0 fp32 -> fp16
// ---------------------------------------------------------------------------
__global__ void __launch_bounds__(256) h0_conv_kernel(const float* __restrict__ h0)
{
    int i = blockIdx.x * 256 + threadIdx.x;
    g_h016[i] = __float2half(h0[i]);
}

// ---------------------------------------------------------------------------
// Templated HMMA GEMM + epilogue.  Occ=2, 3-stage cp.async pipeline:
//   BN=false: A=g_a16 [M][512],  B=g_wt16 [4096][512],  out=g_xz (+bias)
//   BN=true : A=g_hs_h [M][1024],B=g_wdt_h [V][1024],   out=outp (BN epi)
// Dyn smem: 3 bufs x 32KB = 98304, sc/sf -> 99328 B (x2 CTAs = 198656 < 227K)
// ---------------------------------------------------------------------------
template <int KD, bool BN>
__global__ void __launch_bounds__(256, 2) mma_epi_kernel(
    const float* __restrict__ bias, const float* __restrict__ gamma,
    const float* __restrict__ beta, const float* __restrict__ mmean,
    const float* __restrict__ mvar, float* __restrict__ outp, int ldo)
{
    extern __shared__ char smem[];
    const int tid = threadIdx.x;
    const int wid = tid >> 5, l = tid & 31;
    const int wr = wid & 3, wc = wid >> 2;
    const int m0 = blockIdx.y << 7;
    const int n0 = blockIdx.x << 7;
    constexpr int CH = KD / 64;   // 8 or 16 (both >= 3)

    const __half* Ag0 = BN ? g_hs_h : g_a16;
    const __half* Bg0 = BN ? g_wdt_h : g_wt16;
    float* op = BN ? outp : g_xz;

    float* sc = (float*)(smem + 98304);
    float* sf = (float*)(smem + 98816);
    if (tid < 128) {
        int n = n0 + tid;
        float scv = 1.0f, sfv = bias[n];
        if (BN) {
            float iv = gamma[n] * rsqrtf(mvar[n] + 1e-3f);
            scv = iv;
            sfv = beta[n] + (bias[n] - mmean[n]) * iv;
        }
        sc[tid] = scv;
        sf[tid] = sfv;
    }

    const uint32_t sb = smem_u32(smem);
    const __half* Ag = Ag0 + (size_t)m0 * KD;
    const __half* Bg = Bg0 + (size_t)n0 * KD;

    auto load_chunk = [&](int c) {
        const int k0 = c << 6;
        const uint32_t base = sb + (c % 3) * 32768;
#pragma unroll
        for (int q = 0; q < 4; q++) {
            int u = q * 256 + tid;
            int row = u >> 3, un = u & 7;
            uint32_t off = SWZ(row * 128 + un * 16);
            cpa16(base + off,         Ag + (size_t)row * KD + k0 + un * 8);
            cpa16(base + 16384 + off, Bg + (size_t)row * KD + k0 + un * 8);
        }
        asm volatile("cp.async.commit_group;" ::: "memory");
    };

    float acc[2][8][4];
#pragma unroll
    for (int mi = 0; mi < 2; mi++)
#pragma unroll
        for (int ni = 0; ni < 8; ni++)
#pragma unroll
            for (int k = 0; k < 4; k++) acc[mi][ni][k] = 0.0f;

    load_chunk(0);
    load_chunk(1);
    load_chunk(2);

    for (int c = 0; c < CH; c++) {
        if (c + 2 < CH)      asm volatile("cp.async.wait_group 2;" ::: "memory");
        else if (c + 1 < CH) asm volatile("cp.async.wait_group 1;" ::: "memory");
        else                 asm volatile("cp.async.wait_group 0;" ::: "memory");
        __syncthreads();

        const uint32_t base = sb + (c % 3) * 32768;
#pragma unroll
        for (int kss = 0; kss < 4; kss++) {
            uint32_t a[2][4];
#pragma unroll
            for (int mi = 0; mi < 2; mi++) {
                int row = wr * 32 + mi * 16 + (l & 15);
                int un  = kss * 2 + (l >> 4);
                uint32_t addr = base + SWZ(row * 128 + un * 16);
                asm volatile("ldmatrix.sync.aligned.m8n8.x4.shared.b16 {%0,%1,%2,%3}, [%4];"
                             : "=r"(a[mi][0]), "=r"(a[mi][1]), "=r"(a[mi][2]), "=r"(a[mi][3])
                             : "r"(addr));
            }
            uint32_t bf[4][4];
#pragma unroll
            for (int nb = 0; nb < 4; nb++) {
                int row = wc * 64 + nb * 16 + ((l >> 4) << 3) + (l & 7);
                int un  = kss * 2 + ((l >> 3) & 1);
                uint32_t addr = base + 16384 + SWZ(row * 128 + un * 16);
                asm volatile("ldmatrix.sync.aligned.m8n8.x4.shared.b16 {%0,%1,%2,%3}, [%4];"
                             : "=r"(bf[nb][0]), "=r"(bf[nb][1]), "=r"(bf[nb][2]), "=r"(bf[nb][3])
                             : "r"(addr));
            }
#pragma unroll
            for (int mi = 0; mi < 2; mi++)
#pragma unroll
                for (int ni = 0; ni < 8; ni++) {
                    uint32_t b0 = bf[ni >> 1][(ni & 1) * 2 + 0];
                    uint32_t b1 = bf[ni >> 1][(ni & 1) * 2 + 1];
                    asm volatile(
                        "mma.sync.aligned.m16n8k16.row.col.f32.f16.f16.f32 "
                        "{%0,%1,%2,%3}, {%4,%5,%6,%7}, {%8,%9}, {%0,%1,%2,%3};"
                        : "+f"(acc[mi][ni][0]), "+f"(acc[mi][ni][1]),
                          "+f"(acc[mi][ni][2]), "+f"(acc[mi][ni][3])
                        : "r"(a[mi][0]), "r"(a[mi][1]), "r"(a[mi][2]), "r"(a[mi][3]),
                          "r"(b0), "r"(b1));
                }
        }
        __syncthreads();
        if (c + 3 < CH) load_chunk(c + 3);
    }

#pragma unroll
    for (int mi = 0; mi < 2; mi++) {
        int r0 = m0 + wr * 32 + mi * 16 + (l >> 2);
#pragma unroll
        for (int ni = 0; ni < 8; ni++) {
            int cl = wc * 64 + ni * 8 + (l & 3) * 2;
            float s0 = sc[cl], s1 = sc[cl + 1];
            float f0 = sf[cl], f1 = sf[cl + 1];
            float2 v0 = make_float2(acc[mi][ni][0] * s0 + f0,
                                    acc[mi][ni][1] * s1 + f1);
            float2 v1 = make_float2(acc[mi][ni][2] * s0 + f0,
                                    acc[mi][ni][3] * s1 + f1);
            *(float2*)(op + (size_t)r0 * ldo + n0 + cl) = v0;
            *(float2*)(op + (size_t)(r0 + 8) * ldo + n0 + cl) = v1;
        }
    }
}

// ---------------------------------------------------------------------------
// Persistent LSTM v4 (HMMA + distributed flag barrier): 128 CTAs, 256 threads.
// Dyn smem: U 65536 + A 65536 + zred 36864 -> 167936 B.
// ---------------------------------------------------------------------------
__global__ void __launch_bounds__(256, 1) lstm_mma_kernel(const float* __restrict__ c0)
{
    extern __shared__ char sm[];
    const uint32_t sb = smem_u32(sm);
    float* zred = (float*)(sm + 131072);     // [8][32][36] fp32, padded

    const int tid = threadIdx.x;
    const int wid = tid >> 5, l = tid & 31;
    const int jbase = blockIdx.x * 8;

    // ---- stage U^T slice once: local row n -> global row (n&3)*1024+jbase+(n>>2)
#pragma unroll
    for (int it = 0; it < 16; it++) {
        int u = it * 256 + tid;              // 0..4095
        int chunk = u >> 8;
        int rem = u & 255;
        int row = rem >> 3, seg = rem & 7;
        int gr = (row & 3) * 1024 + jbase + (row >> 2);
        cpa16(sb + chunk * 4096 + SWZ(row * 128 + seg * 16),
              g_ut16 + (size_t)gr * HH + chunk * 64 + seg * 8);
    }
    asm volatile("cp.async.commit_group;" ::: "memory");

    const int gb = tid >> 3;                 // 0..31
    const int gj = tid & 7;                  // 0..7
    float creg = c0[gb * HH + jbase + gj];

    asm volatile("cp.async.wait_group 0;" ::: "memory");
    __syncthreads();

    for (int t = 0; t < TT; t++) {
        const __half* hsrc = (t == 0) ? g_h016
                                      : (g_hs_h + (size_t)(t - 1) * (BB * HH));
#pragma unroll
        for (int it = 0; it < 16; it++) {
            int u = it * 256 + tid;
            int chunk = u >> 8;
            int rem = u & 255;
            int row = rem >> 3, seg = rem & 7;
            cpa16(sb + 65536 + chunk * 4096 + SWZ(row * 128 + seg * 16),
                  hsrc + (size_t)row * HH + chunk * 64 + seg * 8);
        }
        asm volatile("cp.async.commit_group;" ::: "memory");
        asm volatile("cp.async.wait_group 0;" ::: "memory");
        __syncthreads();

        float acc[2][4][4];
#pragma unroll
        for (int mi = 0; mi < 2; mi++)
#pragma unroll
            for (int ni = 0; ni < 4; ni++)
#pragma unroll
                for (int k = 0; k < 4; k++) acc[mi][ni][k] = 0.0f;

#pragma unroll
        for (int cc = 0; cc < 2; cc++) {
            const uint32_t ab = sb + 65536 + (2 * wid + cc) * 4096;
            const uint32_t bb = sb + (2 * wid + cc) * 4096;
#pragma unroll
            for (int kss = 0; kss < 4; kss++) {
                uint32_t a[2][4];
#pragma unroll
                for (int mi = 0; mi < 2; mi++) {
                    int row = mi * 16 + (l & 15);
                    int un  = kss * 2 + (l >> 4);
                    uint32_t addr = ab + SWZ(row * 128 + un * 16);
                    asm volatile("ldmatrix.sync.aligned.m8n8.x4.shared.b16 {%0,%1,%2,%3}, [%4];"
                                 : "=r"(a[mi][0]), "=r"(a[mi][1]), "=r"(a[mi][2]), "=r"(a[mi][3])
                                 : "r"(addr));
                }
                uint32_t bf[2][4];
#pragma unroll
                for (int nb = 0; nb < 2; nb++) {
                    int row = nb * 16 + ((l >> 4) << 3) + (l & 7);
                    int un  = kss * 2 + ((l >> 3) & 1);
                    uint32_t addr = bb + SWZ(row * 128 + un * 16);
                    asm volatile("ldmatrix.sync.aligned.m8n8.x4.shared.b16 {%0,%1,%2,%3}, [%4];"
                                 : "=r"(bf[nb][0]), "=r"(bf[nb][1]), "=r"(bf[nb][2]), "=r"(bf[nb][3])
                                 : "r"(addr));
                }
#pragma unroll
                for (int mi = 0; mi < 2; mi++)
#pragma unroll
                    for (int ni = 0; ni < 4; ni++) {
                        uint32_t b0 = bf[ni >> 1][(ni & 1) * 2 + 0];
                        uint32_t b1 = bf[ni >> 1][(ni & 1) * 2 + 1];
                        asm volatile(
                            "mma.sync.aligned.m16n8k16.row.col.f32.f16.f16.f32 "
                            "{%0,%1,%2,%3}, {%4,%5,%6,%7}, {%8,%9}, {%0,%1,%2,%3};"
                            : "+f"(acc[mi][ni][0]), "+f"(acc[mi][ni][1]),
                              "+f"(acc[mi][ni][2]), "+f"(acc[mi][ni][3])
                            : "r"(a[mi][0]), "r"(a[mi][1]), "r"(a[mi][2]), "r"(a[mi][3]),
                              "r"(b0), "r"(b1));
                    }
            }
        }

        {
            float* zw = zred + wid * 1152;
#pragma unroll
            for (int mi = 0; mi < 2; mi++)
#pragma unroll
                for (int ni = 0; ni < 4; ni++) {
                    int r = mi * 16 + (l >> 2);
                    int c = ni * 8 + (l & 3) * 2;
                    *(float2*)&zw[r * 36 + c] =
                        make_float2(acc[mi][ni][0], acc[mi][ni][1]);
                    *(float2*)&zw[(r + 8) * 36 + c] =
                        make_float2(acc[mi][ni][2], acc[mi][ni][3]);
                }
        }
        __syncthreads();

        {
            float4 zs = make_float4(0.f, 0.f, 0.f, 0.f);
#pragma unroll
            for (int w = 0; w < 8; w++) {
                float4 v = *(const float4*)&zred[w * 1152 + gb * 36 + (gj << 2)];
                zs.x += v.x; zs.y += v.y; zs.z += v.z; zs.w += v.w;
            }
            const float* xb = g_xz + (size_t)t * BB * GG + (size_t)gb * GG;
            const int j = jbase + gj;
            float zi = zs.x + xb[j];
            float zf = zs.y + xb[HH + j];
            float zg = zs.z + xb[2 * HH + j];
            float zo = zs.w + xb[3 * HH + j];
            float cn = sigm(zf) * creg + sigm(zi) * tanhf(zg);
            float hn = sigm(zo) * tanhf(cn);
            creg = cn;
            g_hs_h[(size_t)t * BB * HH + (size_t)gb * HH + j] = __float2half(hn);
        }

        // ---- distributed flag barrier: CTA i publishes step, all poll in parallel
        __threadfence();
        __syncthreads();                          // all hn stores fenced before flag
        if (tid == 0) __stcg(&g_flags[blockIdx.x], (unsigned)(t + 1));
        if (tid < 128) {
            volatile unsigned* vf = (volatile unsigned*)&g_flags[tid];
            while (*vf < (unsigned)(t + 1)) { }
        }
        __threadfence();                          // acquire before reading peers' h
        __syncthreads();
    }
}

// ---------------------------------------------------------------------------
extern "C" void kernel_launch(void* const* d_in, const int* in_sizes, int n_in,
                              void* d_out, int out_size)
{
    const int*   X     = (const int*)  d_in[0];
    const float* h0    = (const float*)d_in[1];
    const float* c0    = (const float*)d_in[2];
    const float* emb   = (const float*)d_in[3];
    const float* W     = (const float*)d_in[4];
    const float* U     = (const float*)d_in[5];
    const float* b     = (const float*)d_in[6];
    const float* Wd    = (const float*)d_in[7];
    const float* bd    = (const float*)d_in[8];
    const float* gamma = (const float*)d_in[9];
    const float* beta  = (const float*)d_in[10];
    const float* mmean = (const float*)d_in[11];
    const float* mvar  = (const float*)d_in[12];
    float* out = (float*)d_out;

    cudaFuncSetAttribute(lstm_mma_kernel,
                         cudaFuncAttributeMaxDynamicSharedMemorySize, 167936);
    cudaFuncSetAttribute(mma_epi_kernel<512, false>,
                         cudaFuncAttributeMaxDynamicSharedMemorySize, 99328);
    cudaFuncSetAttribute(mma_epi_kernel<1024, true>,
                         cudaFuncAttributeMaxDynamicSharedMemorySize, 99328);

    init_bar_kernel<<<1, 128>>>();

    // preps
    gather_conv_kernel<<<MM, 128>>>(X, emb);
    wt_conv_kernel<<<dim3(GG / 32, EE / 32), 256>>>(W);
    ut_conv_kernel<<<dim3(GG / 32, HH / 32), 256>>>(U);
    wd_split_kernel<<<dim3(VV / 32, HH / 32), 256>>>(Wd);
    h0_conv_kernel<<<(BB * HH) / 256, 256>>>(h0);

    // Xz = emb[X]@W + b  (HMMA fp16; writes g_xz internally)
    mma_epi_kernel<512, false><<<dim3(GG / 128, MM / 128), 256, 99328>>>(
        b, nullptr, nullptr, nullptr, nullptr, nullptr, GG);

    // persistent HMMA LSTM over all 128 steps
    lstm_mma_kernel<<<128, 256, 167936>>>(c0);

    // projection + BN (HMMA fp16)
    mma_epi_kernel<1024, true><<<dim3(VV / 128, MM / 128), 256, 99328>>>(
        bd, gamma, beta, mmean, mvar, out, VV);
}

// round 15
// speedup vs baseline: 1.5281x; 1.5281x over previous
#include <cuda_runtime.h>
#include <cuda_fp16.h>
#include <math.h>
#include <stdint.h>

// Shapes (fixed): B=32, T=128, V=32000, E=512, H=1024, 4H=4096
#define BB 32
#define TT 128
#define VV 32000
#define EE 512
#define HH 1024
#define GG 4096
#define MM 4096   // T*B rows

// ------------------------- static device scratch ---------------------------
__device__ float  g_xz[(size_t)MM * GG];        // emb[X]@W + b  (64 MB)
__device__ __half g_hs_h[(size_t)MM * HH];      // hs fp16 archive (8 MB) — also h state
__device__ __half g_h016[BB * HH];              // h0 fp16
__device__ __half g_wdt_h[(size_t)VV * HH];     // Wd^T fp16 [V][K] (64 MB)
__device__ __half g_a16[(size_t)MM * EE];       // gathered emb fp16 (4 MB)
__device__ __half g_wt16[(size_t)GG * EE];      // W^T fp16 [4H][E] (4 MB)
__device__ __half g_ut16[(size_t)GG * HH];      // U^T fp16 [4H][H] (8 MB)
__device__ unsigned g_bar;                      // persistent-kernel barrier

__device__ __forceinline__ float sigm(float x) { return 1.0f / (1.0f + expf(-x)); }

__device__ __forceinline__ uint32_t smem_u32(const void* p) {
    uint32_t a;
    asm("{ .reg .u64 t; cvta.to.shared.u64 t, %1; cvt.u32.u64 %0, t; }"
        : "=r"(a) : "l"(p));
    return a;
}
__device__ __forceinline__ void cpa16(uint32_t d, const void* s) {
    asm volatile("cp.async.cg.shared.global [%0], [%1], 16;" :: "r"(d), "l"(s));
}
#define SWZ(x) ((x) ^ (((x) >> 3) & 0x70))

// ---------------------------------------------------------------------------
__global__ void init_bar_kernel() { g_bar = 0u; }

// ---------------------------------------------------------------------------
// Prep A: gather emb rows -> fp16, row r = t*32+b
// ---------------------------------------------------------------------------
__global__ void __launch_bounds__(128) gather_conv_kernel(
    const int* __restrict__ X, const float* __restrict__ emb)
{
    const int r = blockIdx.x;
    const int t = r >> 5, b = r & 31;
    const int e = X[b * TT + t];
    float4 v = ((const float4*)(emb + (size_t)e * EE))[threadIdx.x];
    __half2 h01 = __floats2half2_rn(v.x, v.y);
    __half2 h23 = __floats2half2_rn(v.z, v.w);
    uint2 pk;
    pk.x = *(uint32_t*)&h01;
    pk.y = *(uint32_t*)&h23;
    *(uint2*)(g_a16 + (size_t)r * EE + threadIdx.x * 4) = pk;
}

// ---------------------------------------------------------------------------
// Prep B: W [E=512][4H] -> W^T fp16 [4H][E]
// ---------------------------------------------------------------------------
__global__ void __launch_bounds__(256) wt_conv_kernel(const float* __restrict__ W)
{
    __shared__ float tb[32][33];
    const int n0 = blockIdx.x * 32;
    const int k0 = blockIdx.y * 32;
    const int tx = threadIdx.x & 31;
    const int ty0 = threadIdx.x >> 5;
#pragma unroll
    for (int ty = ty0; ty < 32; ty += 8)
        tb[ty][tx] = W[(size_t)(k0 + ty) * GG + n0 + tx];
    __syncthreads();
#pragma unroll
    for (int ty = ty0; ty < 32; ty += 8)
        g_wt16[(size_t)(n0 + ty) * EE + k0 + tx] = __float2half(tb[tx][ty]);
}

// ---------------------------------------------------------------------------
// Prep B2: U [H=1024][4H] -> U^T fp16 [4H][H]
// ---------------------------------------------------------------------------
__global__ void __launch_bounds__(256) ut_conv_kernel(const float* __restrict__ U)
{
    __shared__ float tb[32][33];
    const int n0 = blockIdx.x * 32;
    const int k0 = blockIdx.y * 32;
    const int tx = threadIdx.x & 31;
    const int ty0 = threadIdx.x >> 5;
#pragma unroll
    for (int ty = ty0; ty < 32; ty += 8)
        tb[ty][tx] = U[(size_t)(k0 + ty) * GG + n0 + tx];
    __syncthreads();
#pragma unroll
    for (int ty = ty0; ty < 32; ty += 8)
        g_ut16[(size_t)(n0 + ty) * HH + k0 + tx] = __float2half(tb[tx][ty]);
}

// ---------------------------------------------------------------------------
// Prep C: Wd [K=1024][V] -> Wd^T fp16 [V][K]
// ---------------------------------------------------------------------------
__global__ void __launch_bounds__(256) wd_split_kernel(const float* __restrict__ Wd)
{
    __shared__ float tb[32][33];
    const int v0 = blockIdx.x * 32;
    const int k0 = blockIdx.y * 32;
    const int tx = threadIdx.x & 31;
    const int ty0 = threadIdx.x >> 5;
#pragma unroll
    for (int ty = ty0; ty < 32; ty += 8)
        tb[ty][tx] = Wd[(size_t)(k0 + ty) * VV + v0 + tx];
    __syncthreads();
#pragma unroll
    for (int ty = ty0; ty < 32; ty += 8)
        g_wdt_h[(size_t)(v0 + ty) * HH + k0 + tx] = __float2half(tb[tx][ty]);
}

// ---------------------------------------------------------------------------
// Prep D: h0 fp32 -> fp16
// ---------------------------------------------------------------------------
__global__ void __launch_bounds__(256) h0_conv_kernel(const float* __restrict__ h0)
{
    int i = blockIdx.x * 256 + threadIdx.x;
    g_h016[i] = __float2half(h0[i]);
}

// ---------------------------------------------------------------------------
// Templated HMMA GEMM + epilogue.  Occ=2, 2-stage pipeline (R13 config).
//   Grid: x = M-tile (fastest) so one wave spans all M for few N-tiles ->
//   each B tile is fetched to L2 once and reused by all co-resident M-tiles.
//   BN=false: A=g_a16 [M][512],  B=g_wt16 [4096][512],  out=g_xz (+bias)
//   BN=true : A=g_hs_h [M][1024],B=g_wdt_h [V][1024],   out=outp (BN epi)
// ---------------------------------------------------------------------------
template <int KD, bool BN>
__global__ void __launch_bounds__(256, 2) mma_epi_kernel(
    const float* __restrict__ bias, const float* __restrict__ gamma,
    const float* __restrict__ beta, const float* __restrict__ mmean,
    const float* __restrict__ mvar, float* __restrict__ outp, int ldo)
{
    extern __shared__ char smem[];
    const int tid = threadIdx.x;
    const int wid = tid >> 5, l = tid & 31;
    const int wr = wid & 3, wc = wid >> 2;
    const int m0 = blockIdx.x << 7;     // M fastest-varying across CTAs
    const int n0 = blockIdx.y << 7;
    constexpr int CH = KD / 64;

    const __half* Ag0 = BN ? g_hs_h : g_a16;
    const __half* Bg0 = BN ? g_wdt_h : g_wt16;
    float* op = BN ? outp : g_xz;

    float* sc = (float*)(smem + 65536);
    float* sf = (float*)(smem + 66048);
    if (tid < 128) {
        int n = n0 + tid;
        float scv = 1.0f, sfv = bias[n];
        if (BN) {
            float iv = gamma[n] * rsqrtf(mvar[n] + 1e-3f);
            scv = iv;
            sfv = beta[n] + (bias[n] - mmean[n]) * iv;
        }
        sc[tid] = scv;
        sf[tid] = sfv;
    }

    const uint32_t sb = smem_u32(smem);
    const __half* Ag = Ag0 + (size_t)m0 * KD;
    const __half* Bg = Bg0 + (size_t)n0 * KD;

    auto load_chunk = [&](int c) {
        const int k0 = c << 6;
        const uint32_t base = sb + (c & 1) * 32768;
#pragma unroll
        for (int q = 0; q < 4; q++) {
            int u = q * 256 + tid;
            int row = u >> 3, un = u & 7;
            uint32_t off = SWZ(row * 128 + un * 16);
            cpa16(base + off,         Ag + (size_t)row * KD + k0 + un * 8);
            cpa16(base + 16384 + off, Bg + (size_t)row * KD + k0 + un * 8);
        }
        asm volatile("cp.async.commit_group;" ::: "memory");
    };

    float acc[2][8][4];
#pragma unroll
    for (int mi = 0; mi < 2; mi++)
#pragma unroll
        for (int ni = 0; ni < 8; ni++)
#pragma unroll
            for (int k = 0; k < 4; k++) acc[mi][ni][k] = 0.0f;

    load_chunk(0);
    load_chunk(1);

    for (int c = 0; c < CH; c++) {
        if (c < CH - 1) asm volatile("cp.async.wait_group 1;" ::: "memory");
        else            asm volatile("cp.async.wait_group 0;" ::: "memory");
        __syncthreads();

        const uint32_t base = sb + (c & 1) * 32768;
#pragma unroll
        for (int kss = 0; kss < 4; kss++) {
            uint32_t a[2][4];
#pragma unroll
            for (int mi = 0; mi < 2; mi++) {
                int row = wr * 32 + mi * 16 + (l & 15);
                int un  = kss * 2 + (l >> 4);
                uint32_t addr = base + SWZ(row * 128 + un * 16);
                asm volatile("ldmatrix.sync.aligned.m8n8.x4.shared.b16 {%0,%1,%2,%3}, [%4];"
                             : "=r"(a[mi][0]), "=r"(a[mi][1]), "=r"(a[mi][2]), "=r"(a[mi][3])
                             : "r"(addr));
            }
            uint32_t bf[4][4];
#pragma unroll
            for (int nb = 0; nb < 4; nb++) {
                int row = wc * 64 + nb * 16 + ((l >> 4) << 3) + (l & 7);
                int un  = kss * 2 + ((l >> 3) & 1);
                uint32_t addr = base + 16384 + SWZ(row * 128 + un * 16);
                asm volatile("ldmatrix.sync.aligned.m8n8.x4.shared.b16 {%0,%1,%2,%3}, [%4];"
                             : "=r"(bf[nb][0]), "=r"(bf[nb][1]), "=r"(bf[nb][2]), "=r"(bf[nb][3])
                             : "r"(addr));
            }
#pragma unroll
            for (int mi = 0; mi < 2; mi++)
#pragma unroll
                for (int ni = 0; ni < 8; ni++) {
                    uint32_t b0 = bf[ni >> 1][(ni & 1) * 2 + 0];
                    uint32_t b1 = bf[ni >> 1][(ni & 1) * 2 + 1];
                    asm volatile(
                        "mma.sync.aligned.m16n8k16.row.col.f32.f16.f16.f32 "
                        "{%0,%1,%2,%3}, {%4,%5,%6,%7}, {%8,%9}, {%0,%1,%2,%3};"
                        : "+f"(acc[mi][ni][0]), "+f"(acc[mi][ni][1]),
                          "+f"(acc[mi][ni][2]), "+f"(acc[mi][ni][3])
                        : "r"(a[mi][0]), "r"(a[mi][1]), "r"(a[mi][2]), "r"(a[mi][3]),
                          "r"(b0), "r"(b1));
                }
        }
        __syncthreads();
        if (c + 2 < CH) load_chunk(c + 2);
    }

#pragma unroll
    for (int mi = 0; mi < 2; mi++) {
        int r0 = m0 + wr * 32 + mi * 16 + (l >> 2);
#pragma unroll
        for (int ni = 0; ni < 8; ni++) {
            int cl = wc * 64 + ni * 8 + (l & 3) * 2;
            float s0 = sc[cl], s1 = sc[cl + 1];
            float f0 = sf[cl], f1 = sf[cl + 1];
            float2 v0 = make_float2(acc[mi][ni][0] * s0 + f0,
                                    acc[mi][ni][1] * s1 + f1);
            float2 v1 = make_float2(acc[mi][ni][2] * s0 + f0,
                                    acc[mi][ni][3] * s1 + f1);
            *(float2*)(op + (size_t)r0 * ldo + n0 + cl) = v0;
            *(float2*)(op + (size_t)(r0 + 8) * ldo + n0 + cl) = v1;
        }
    }
}

// ---------------------------------------------------------------------------
// Persistent LSTM v3 (HMMA, exact R13 version incl. single-counter barrier):
// 128 CTAs, 256 threads.  Dyn smem: U 65536 + A 65536 + zred 36864 -> 167936 B.
// ---------------------------------------------------------------------------
__global__ void __launch_bounds__(256, 1) lstm_mma_kernel(const float* __restrict__ c0)
{
    extern __shared__ char sm[];
    const uint32_t sb = smem_u32(sm);
    float* zred = (float*)(sm + 131072);     // [8][32][36] fp32, padded

    const int tid = threadIdx.x;
    const int wid = tid >> 5, l = tid & 31;
    const int jbase = blockIdx.x * 8;

    // ---- stage U^T slice once: local row n -> global row (n&3)*1024+jbase+(n>>2)
#pragma unroll
    for (int it = 0; it < 16; it++) {
        int u = it * 256 + tid;              // 0..4095
        int chunk = u >> 8;
        int rem = u & 255;
        int row = rem >> 3, seg = rem & 7;
        int gr = (row & 3) * 1024 + jbase + (row >> 2);
        cpa16(sb + chunk * 4096 + SWZ(row * 128 + seg * 16),
              g_ut16 + (size_t)gr * HH + chunk * 64 + seg * 8);
    }
    asm volatile("cp.async.commit_group;" ::: "memory");

    const int gb = tid >> 3;                 // 0..31
    const int gj = tid & 7;                  // 0..7
    float creg = c0[gb * HH + jbase + gj];

    asm volatile("cp.async.wait_group 0;" ::: "memory");
    __syncthreads();

    for (int t = 0; t < TT; t++) {
        const __half* hsrc = (t == 0) ? g_h016
                                      : (g_hs_h + (size_t)(t - 1) * (BB * HH));
#pragma unroll
        for (int it = 0; it < 16; it++) {
            int u = it * 256 + tid;
            int chunk = u >> 8;
            int rem = u & 255;
            int row = rem >> 3, seg = rem & 7;
            cpa16(sb + 65536 + chunk * 4096 + SWZ(row * 128 + seg * 16),
                  hsrc + (size_t)row * HH + chunk * 64 + seg * 8);
        }
        asm volatile("cp.async.commit_group;" ::: "memory");
        asm volatile("cp.async.wait_group 0;" ::: "memory");
        __syncthreads();

        float acc[2][4][4];
#pragma unroll
        for (int mi = 0; mi < 2; mi++)
#pragma unroll
            for (int ni = 0; ni < 4; ni++)
#pragma unroll
                for (int k = 0; k < 4; k++) acc[mi][ni][k] = 0.0f;

#pragma unroll
        for (int cc = 0; cc < 2; cc++) {
            const uint32_t ab = sb + 65536 + (2 * wid + cc) * 4096;
            const uint32_t bb = sb + (2 * wid + cc) * 4096;
#pragma unroll
            for (int kss = 0; kss < 4; kss++) {
                uint32_t a[2][4];
#pragma unroll
                for (int mi = 0; mi < 2; mi++) {
                    int row = mi * 16 + (l & 15);
                    int un  = kss * 2 + (l >> 4);
                    uint32_t addr = ab + SWZ(row * 128 + un * 16);
                    asm volatile("ldmatrix.sync.aligned.m8n8.x4.shared.b16 {%0,%1,%2,%3}, [%4];"
                                 : "=r"(a[mi][0]), "=r"(a[mi][1]), "=r"(a[mi][2]), "=r"(a[mi][3])
                                 : "r"(addr));
                }
                uint32_t bf[2][4];
#pragma unroll
                for (int nb = 0; nb < 2; nb++) {
                    int row = nb * 16 + ((l >> 4) << 3) + (l & 7);
                    int un  = kss * 2 + ((l >> 3) & 1);
                    uint32_t addr = bb + SWZ(row * 128 + un * 16);
                    asm volatile("ldmatrix.sync.aligned.m8n8.x4.shared.b16 {%0,%1,%2,%3}, [%4];"
                                 : "=r"(bf[nb][0]), "=r"(bf[nb][1]), "=r"(bf[nb][2]), "=r"(bf[nb][3])
                                 : "r"(addr));
                }
#pragma unroll
                for (int mi = 0; mi < 2; mi++)
#pragma unroll
                    for (int ni = 0; ni < 4; ni++) {
                        uint32_t b0 = bf[ni >> 1][(ni & 1) * 2 + 0];
                        uint32_t b1 = bf[ni >> 1][(ni & 1) * 2 + 1];
                        asm volatile(
                            "mma.sync.aligned.m16n8k16.row.col.f32.f16.f16.f32 "
                            "{%0,%1,%2,%3}, {%4,%5,%6,%7}, {%8,%9}, {%0,%1,%2,%3};"
                            : "+f"(acc[mi][ni][0]), "+f"(acc[mi][ni][1]),
                              "+f"(acc[mi][ni][2]), "+f"(acc[mi][ni][3])
                            : "r"(a[mi][0]), "r"(a[mi][1]), "r"(a[mi][2]), "r"(a[mi][3]),
                              "r"(b0), "r"(b1));
                    }
            }
        }

        {
            float* zw = zred + wid * 1152;
#pragma unroll
            for (int mi = 0; mi < 2; mi++)
#pragma unroll
                for (int ni = 0; ni < 4; ni++) {
                    int r = mi * 16 + (l >> 2);
                    int c = ni * 8 + (l & 3) * 2;
                    *(float2*)&zw[r * 36 + c] =
                        make_float2(acc[mi][ni][0], acc[mi][ni][1]);
                    *(float2*)&zw[(r + 8) * 36 + c] =
                        make_float2(acc[mi][ni][2], acc[mi][ni][3]);
                }
        }
        __syncthreads();

        {
            float4 zs = make_float4(0.f, 0.f, 0.f, 0.f);
#pragma unroll
            for (int w = 0; w < 8; w++) {
                float4 v = *(const float4*)&zred[w * 1152 + gb * 36 + (gj << 2)];
                zs.x += v.x; zs.y += v.y; zs.z += v.z; zs.w += v.w;
            }
            const float* xb = g_xz + (size_t)t * BB * GG + (size_t)gb * GG;
            const int j = jbase + gj;
            float zi = zs.x + xb[j];
            float zf = zs.y + xb[HH + j];
            float zg = zs.z + xb[2 * HH + j];
            float zo = zs.w + xb[3 * HH + j];
            float cn = sigm(zf) * creg + sigm(zi) * tanhf(zg);
            float hn = sigm(zo) * tanhf(cn);
            creg = cn;
            g_hs_h[(size_t)t * BB * HH + (size_t)gb * HH + j] = __float2half(hn);
        }

        __threadfence();
        __syncthreads();
        if (tid == 0) {
            atomicAdd(&g_bar, 1u);
            const unsigned target = 128u * (unsigned)(t + 1);
            volatile unsigned* vb = &g_bar;
            while (*vb < target) { }
        }
        __syncthreads();
    }
}

// ---------------------------------------------------------------------------
extern "C" void kernel_launch(void* const* d_in, const int* in_sizes, int n_in,
                              void* d_out, int out_size)
{
    const int*   X     = (const int*)  d_in[0];
    const float* h0    = (const float*)d_in[1];
    const float* c0    = (const float*)d_in[2];
    const float* emb   = (const float*)d_in[3];
    const float* W     = (const float*)d_in[4];
    const float* U     = (const float*)d_in[5];
    const float* b     = (const float*)d_in[6];
    const float* Wd    = (const float*)d_in[7];
    const float* bd    = (const float*)d_in[8];
    const float* gamma = (const float*)d_in[9];
    const float* beta  = (const float*)d_in[10];
    const float* mmean = (const float*)d_in[11];
    const float* mvar  = (const float*)d_in[12];
    float* out = (float*)d_out;

    cudaFuncSetAttribute(lstm_mma_kernel,
                         cudaFuncAttributeMaxDynamicSharedMemorySize, 167936);
    cudaFuncSetAttribute(mma_epi_kernel<512, false>,
                         cudaFuncAttributeMaxDynamicSharedMemorySize, 66560);
    cudaFuncSetAttribute(mma_epi_kernel<1024, true>,
                         cudaFuncAttributeMaxDynamicSharedMemorySize, 66560);

    init_bar_kernel<<<1, 1>>>();

    // preps
    gather_conv_kernel<<<MM, 128>>>(X, emb);
    wt_conv_kernel<<<dim3(GG / 32, EE / 32), 256>>>(W);
    ut_conv_kernel<<<dim3(GG / 32, HH / 32), 256>>>(U);
    wd_split_kernel<<<dim3(VV / 32, HH / 32), 256>>>(Wd);
    h0_conv_kernel<<<(BB * HH) / 256, 256>>>(h0);

    // Xz = emb[X]@W + b  (HMMA fp16; grid x = M-tiles)
    mma_epi_kernel<512, false><<<dim3(MM / 128, GG / 128), 256, 66560>>>(
        b, nullptr, nullptr, nullptr, nullptr, nullptr, GG);

    // persistent HMMA LSTM over all 128 steps
    lstm_mma_kernel<<<128, 256, 167936>>>(c0);

    // projection + BN (HMMA fp16; grid x = M-tiles for L2 B-reuse)
    mma_epi_kernel<1024, true><<<dim3(MM / 128, VV / 128), 256, 66560>>>(
        bd, gamma, beta, mmean, mvar, out, VV);
}